// round 2
// baseline (speedup 1.0000x reference)
#include <cuda_runtime.h>

// Problem constants
#define N_TOK  262144
#define K_CB   1024
#define D_EMB  64
#define DECAY  0.99f
#define EPSV   1e-5f
#define COMMIT 0.25f

// Output layout (all float32, concatenated in reference return order)
#define OFF_Q    0
#define OFF_LOSS 16777216
#define OFF_IDX  16777217
#define OFF_CB   17039361   // NOTE: odd -> only 4-byte aligned!
#define OFF_CS   17104897
#define OFF_EW   17105921   // NOTE: odd -> only 4-byte aligned!

// Scratch (device globals; no allocations allowed)
__device__ float g_dw[K_CB * D_EMB];
__device__ float g_counts[K_CB];
__device__ float g_loss;
__device__ float g_cnorm[K_CB];

// ---------------------------------------------------------------------------
// Zero scratch (must run each launch: graph replays require determinism)
// ---------------------------------------------------------------------------
__global__ void vq_zero_kernel() {
    int i = blockIdx.x * blockDim.x + threadIdx.x;
    if (i < K_CB * D_EMB) g_dw[i] = 0.0f;
    if (i < K_CB)         g_counts[i] = 0.0f;
    if (i == 0)           g_loss = 0.0f;
}

// ---------------------------------------------------------------------------
// Precompute ||c||^2 for each code
// ---------------------------------------------------------------------------
__global__ void vq_cnorm_kernel(const float* __restrict__ codebook) {
    int k = blockIdx.x * blockDim.x + threadIdx.x;
    if (k >= K_CB) return;
    const float4* c = reinterpret_cast<const float4*>(codebook + k * D_EMB);
    float s0 = 0.f, s1 = 0.f, s2 = 0.f, s3 = 0.f;
#pragma unroll
    for (int i = 0; i < D_EMB / 4; i++) {
        float4 v = c[i];
        s0 += v.x * v.x; s1 += v.y * v.y;
        s2 += v.z * v.z; s3 += v.w * v.w;
    }
    g_cnorm[k] = (s0 + s1) + (s2 + s3);
}

// ---------------------------------------------------------------------------
// Main fused kernel: argmin + quantized gather + counts + dw + loss partial
// One thread = one input vector (x kept in registers).
// Codebook streamed through shared memory in 128-code chunks.
// ---------------------------------------------------------------------------
#define TPB   128
#define CHUNK 128

__global__ void __launch_bounds__(TPB)
vq_assign_kernel(const float* __restrict__ inputs,
                 const float* __restrict__ codebook,
                 float* __restrict__ out) {
    __shared__ float s_c[CHUNK * D_EMB];   // 32 KB: code chunk
    __shared__ float s_cn[CHUNK];          // chunk code norms
    __shared__ float s_counts[K_CB];       // 4 KB: per-block count aggregation
    __shared__ float s_red[TPB / 32];

    const int tid = threadIdx.x;
    const int gid = blockIdx.x * TPB + tid;   // N_TOK == gridDim.x * TPB exactly

    // zero block-local counts (synced by first __syncthreads in chunk loop)
    for (int i = tid; i < K_CB; i += TPB) s_counts[i] = 0.0f;

    // load my input vector into registers (16 x float4 = 64 floats)
    float4 x[16];
    const float4* xp = reinterpret_cast<const float4*>(inputs + (size_t)gid * D_EMB);
#pragma unroll
    for (int i = 0; i < 16; i++) x[i] = xp[i];

    float best = 3.4028235e38f;
    int   bidx = 0;

    for (int ch = 0; ch < K_CB / CHUNK; ch++) {
        __syncthreads();
        // cooperative load of 128 codes (2048 float4 with 128 threads -> 16 each)
        const float4* cp = reinterpret_cast<const float4*>(codebook + (size_t)ch * CHUNK * D_EMB);
        float4* scp = reinterpret_cast<float4*>(s_c);
#pragma unroll
        for (int i = 0; i < (CHUNK * D_EMB / 4) / TPB; i++)
            scp[tid + i * TPB] = cp[tid + i * TPB];
        if (tid < CHUNK) s_cn[tid] = g_cnorm[ch * CHUNK + tid];
        __syncthreads();

        for (int j = 0; j < CHUNK; j++) {
            const float4* csh = reinterpret_cast<const float4*>(s_c + j * D_EMB);
            float s0 = 0.f, s1 = 0.f, s2 = 0.f, s3 = 0.f;
#pragma unroll
            for (int i = 0; i < 16; i++) {
                float4 c4 = csh[i];   // broadcast LDS.128 across the warp
                s0 += x[i].x * c4.x;
                s1 += x[i].y * c4.y;
                s2 += x[i].z * c4.z;
                s3 += x[i].w * c4.w;
            }
            float dot = (s0 + s1) + (s2 + s3);
            float d = s_cn[j] - 2.0f * dot;   // ||x||^2 constant -> omitted
            if (d < best) { best = d; bidx = ch * CHUNK + j; }  // strict < keeps first (JAX argmin tie rule)
        }
    }

    // per-block count aggregation
    atomicAdd(&s_counts[bidx], 1.0f);

    // gather chosen code (L2-resident), write quantized, accumulate loss & dw
    const float4* cchosen = reinterpret_cast<const float4*>(codebook + (size_t)bidx * D_EMB);
    float4* qout = reinterpret_cast<float4*>(out + OFF_Q + (size_t)gid * D_EMB);
    float*  dwrow = g_dw + (size_t)bidx * D_EMB;
    float lsum = 0.0f;
#pragma unroll
    for (int i = 0; i < 16; i++) {
        float4 c4 = cchosen[i];
        qout[i] = c4;
        float dx = c4.x - x[i].x, dy = c4.y - x[i].y;
        float dz = c4.z - x[i].z, dw = c4.w - x[i].w;
        lsum += dx * dx + dy * dy + dz * dz + dw * dw;
        atomicAdd(dwrow + 4 * i + 0, x[i].x);
        atomicAdd(dwrow + 4 * i + 1, x[i].y);
        atomicAdd(dwrow + 4 * i + 2, x[i].z);
        atomicAdd(dwrow + 4 * i + 3, x[i].w);
    }

    // encoding index (cast to float, exactly representable: < 1024)
    out[OFF_IDX + gid] = (float)bidx;

    // block-reduce loss partial -> one global atomic per block
#pragma unroll
    for (int o = 16; o > 0; o >>= 1)
        lsum += __shfl_xor_sync(0xFFFFFFFFu, lsum, o);
    if ((tid & 31) == 0) s_red[tid >> 5] = lsum;
    __syncthreads();
    if (tid == 0) {
        float t = 0.f;
#pragma unroll
        for (int w = 0; w < TPB / 32; w++) t += s_red[w];
        atomicAdd(&g_loss, t);
    }

    // flush block-local counts (atomics above happened before the sync)
    for (int i = tid; i < K_CB; i += TPB) {
        float v = s_counts[i];
        if (v != 0.0f) atomicAdd(&g_counts[i], v);
    }
}

// ---------------------------------------------------------------------------
// Finalize: EMA updates, normalization, loss. One block of K threads.
// NOTE: out+OFF_CB and out+OFF_EW are only 4-byte aligned (odd offsets) ->
// must use scalar stores there.
// ---------------------------------------------------------------------------
__global__ void __launch_bounds__(K_CB)
vq_finalize_kernel(const float* __restrict__ ema_cs,
                   const float* __restrict__ ema_w,
                   float* __restrict__ out) {
    __shared__ float s_n[K_CB];
    const int k = threadIdx.x;

    float ncs = DECAY * ema_cs[k] + (1.0f - DECAY) * g_counts[k];
    out[OFF_CS + k] = ncs;

    // block reduction for n = sum(new_cluster_size)
    s_n[k] = ncs;
    __syncthreads();
#pragma unroll
    for (int s = K_CB / 2; s > 0; s >>= 1) {
        if (k < s) s_n[k] += s_n[k + s];
        __syncthreads();
    }
    float n = s_n[0];

    float smoothed = (ncs + EPSV) / (n + (float)K_CB * EPSV) * n;
    float inv_sm = 1.0f / smoothed;

    // vector loads (bases 16B-aligned), scalar stores (dest 4B-aligned only)
    const float4* ewp = reinterpret_cast<const float4*>(ema_w + (size_t)k * D_EMB);
    const float4* dwp = reinterpret_cast<const float4*>(g_dw + (size_t)k * D_EMB);
    float* o_ew = out + OFF_EW + (size_t)k * D_EMB;
    float* o_cb = out + OFF_CB + (size_t)k * D_EMB;
#pragma unroll
    for (int i = 0; i < D_EMB / 4; i++) {
        float4 e = ewp[i];
        float4 d = dwp[i];
        float wx = DECAY * e.x + (1.0f - DECAY) * d.x;
        float wy = DECAY * e.y + (1.0f - DECAY) * d.y;
        float wz = DECAY * e.z + (1.0f - DECAY) * d.z;
        float ww = DECAY * e.w + (1.0f - DECAY) * d.w;
        o_ew[4 * i + 0] = wx;  o_cb[4 * i + 0] = wx * inv_sm;
        o_ew[4 * i + 1] = wy;  o_cb[4 * i + 1] = wy * inv_sm;
        o_ew[4 * i + 2] = wz;  o_cb[4 * i + 2] = wz * inv_sm;
        o_ew[4 * i + 3] = ww;  o_cb[4 * i + 3] = ww * inv_sm;
    }

    if (k == 0)
        out[OFF_LOSS] = COMMIT * g_loss / (float)((size_t)N_TOK * D_EMB);
}

// ---------------------------------------------------------------------------
extern "C" void kernel_launch(void* const* d_in, const int* in_sizes, int n_in,
                              void* d_out, int out_size) {
    const float* inputs   = (const float*)d_in[0];
    const float* codebook = (const float*)d_in[1];
    const float* ema_cs   = (const float*)d_in[2];
    const float* ema_w    = (const float*)d_in[3];
    float* out = (float*)d_out;

    vq_zero_kernel<<<(K_CB * D_EMB + 255) / 256, 256>>>();
    vq_cnorm_kernel<<<(K_CB + 255) / 256, 256>>>(codebook);
    vq_assign_kernel<<<N_TOK / TPB, TPB>>>(inputs, codebook, out);
    vq_finalize_kernel<<<1, K_CB>>>(ema_cs, ema_w, out);
}

// round 4
// speedup vs baseline: 1.0814x; 1.0814x over previous
#include <cuda_runtime.h>

// Problem constants
#define N_TOK  262144
#define K_CB   1024
#define D_EMB  64
#define DECAY  0.99f
#define EPSV   1e-5f
#define COMMIT 0.25f

// Output layout (float32 blob, reference return order)
#define OFF_Q    0
#define OFF_LOSS 16777216
#define OFF_IDX  16777217
#define OFF_CB   17039361   // odd -> only 4-byte aligned
#define OFF_CS   17104897
#define OFF_EW   17105921   // odd -> only 4-byte aligned

// Scratch (device globals; no allocations allowed)
__device__ float g_dw[K_CB * D_EMB];
__device__ float g_counts[K_CB];
__device__ float g_loss;
__device__ float g_cnorm[K_CB];
__device__ float g_n;

typedef unsigned long long u64;

// ---- packed f32x2 helpers (sm_103a; per-lane IEEE rounding == scalar FFMA) -
__device__ __forceinline__ void ffma2(u64& d, u64 a, u64 b) {
    asm("fma.rn.f32x2 %0, %1, %2, %0;" : "+l"(d) : "l"(a), "l"(b));
}
__device__ __forceinline__ float2 unpack2(u64 v) {
    float2 r; asm("mov.b64 {%0, %1}, %2;" : "=f"(r.x), "=f"(r.y) : "l"(v)); return r;
}

// ---------------------------------------------------------------------------
// Zero scratch (graph replays require determinism)
// ---------------------------------------------------------------------------
__global__ void vq_zero_kernel() {
    int i = blockIdx.x * blockDim.x + threadIdx.x;
    if (i < K_CB * D_EMB) g_dw[i] = 0.0f;
    if (i < K_CB)         g_counts[i] = 0.0f;
    if (i == 0)           g_loss = 0.0f;
}

// ---------------------------------------------------------------------------
// Precompute ||c||^2 per code (identical arithmetic to the R2 passing kernel)
// ---------------------------------------------------------------------------
__global__ void vq_cnorm_kernel(const float* __restrict__ codebook) {
    int k = blockIdx.x * blockDim.x + threadIdx.x;
    if (k >= K_CB) return;
    const float4* c = reinterpret_cast<const float4*>(codebook + k * D_EMB);
    float s0 = 0.f, s1 = 0.f, s2 = 0.f, s3 = 0.f;
#pragma unroll
    for (int i = 0; i < D_EMB / 4; i++) {
        float4 v = c[i];
        s0 += v.x * v.x; s1 += v.y * v.y;
        s2 += v.z * v.z; s3 += v.w * v.w;
    }
    g_cnorm[k] = (s0 + s1) + (s2 + s3);
}

// ---------------------------------------------------------------------------
// Main fused kernel. f32x2 packed math arranged to be BIT-IDENTICAL to the
// R2 scalar version: lane-x of aXY == s0 chain, lane-y == s1, aZW -> s2,s3.
// Final combine: dot=(s0+s1)+(s2+s3); d = cn - 2.0f*dot.
// ---------------------------------------------------------------------------
#define TPB   128
#define CHUNK 128

__global__ void __launch_bounds__(TPB)
vq_assign_kernel(const float* __restrict__ inputs,
                 const float* __restrict__ codebook,
                 float* __restrict__ out) {
    __shared__ float s_c[CHUNK * D_EMB];   // 32 KB code chunk
    __shared__ float s_cn[CHUNK];
    __shared__ float s_counts[K_CB];       // 4 KB per-block count aggregation
    __shared__ float s_red[TPB / 32];

    const int tid = threadIdx.x;
    const int gid = blockIdx.x * TPB + tid;   // N_TOK == gridDim.x * TPB

    for (int i = tid; i < K_CB; i += TPB) s_counts[i] = 0.0f;

    // load my input vector as packed f32x2 pairs (unmodified values)
    ulonglong2 xs[16];
    const ulonglong2* xp = reinterpret_cast<const ulonglong2*>(inputs + (size_t)gid * D_EMB);
#pragma unroll
    for (int i = 0; i < 16; i++) xs[i] = xp[i];

    float best = 3.4028235e38f;
    int   bidx = 0;

    for (int ch = 0; ch < K_CB / CHUNK; ch++) {
        __syncthreads();
        const float4* cp = reinterpret_cast<const float4*>(codebook + (size_t)ch * CHUNK * D_EMB);
        float4* scp = reinterpret_cast<float4*>(s_c);
#pragma unroll
        for (int i = 0; i < (CHUNK * D_EMB / 4) / TPB; i++)
            scp[tid + i * TPB] = cp[tid + i * TPB];
        if (tid < CHUNK) s_cn[tid] = g_cnorm[ch * CHUNK + tid];
        __syncthreads();

#pragma unroll 4
        for (int j = 0; j < CHUNK; j++) {
            const ulonglong2* csh = reinterpret_cast<const ulonglong2*>(s_c + j * D_EMB);
            u64 aXY = 0, aZW = 0;    // lanes: (s0,s1) and (s2,s3)
#pragma unroll
            for (int i = 0; i < 16; i++) {
                ulonglong2 c2 = csh[i];   // LDS.128 broadcast = two f32x2
                ffma2(aXY, xs[i].x, c2.x);
                ffma2(aZW, xs[i].y, c2.y);
            }
            float2 uxy = unpack2(aXY);
            float2 uzw = unpack2(aZW);
            float dot = (uxy.x + uxy.y) + (uzw.x + uzw.y);  // (s0+s1)+(s2+s3)
            float d = s_cn[j] - 2.0f * dot;                  // same as R2
            if (d < best) { best = d; bidx = ch * CHUNK + j; }  // strict <: first-min
        }
    }

    // per-block count aggregation
    atomicAdd(&s_counts[bidx], 1.0f);

    // gather chosen code, write quantized, accumulate loss & dw
    const float4* cchosen = reinterpret_cast<const float4*>(codebook + (size_t)bidx * D_EMB);
    float4* qout = reinterpret_cast<float4*>(out + OFF_Q + (size_t)gid * D_EMB);
    float*  dwrow = g_dw + (size_t)bidx * D_EMB;
    float lsum = 0.0f;
#pragma unroll
    for (int i = 0; i < 16; i++) {
        float4 c4 = cchosen[i];
        qout[i] = c4;
        float2 lo = unpack2(xs[i].x);
        float2 hi = unpack2(xs[i].y);
        float dx = c4.x - lo.x, dy = c4.y - lo.y;
        float dz = c4.z - hi.x, dwv = c4.w - hi.y;
        lsum += dx * dx + dy * dy + dz * dz + dwv * dwv;
        atomicAdd(dwrow + 4 * i + 0, lo.x);
        atomicAdd(dwrow + 4 * i + 1, lo.y);
        atomicAdd(dwrow + 4 * i + 2, hi.x);
        atomicAdd(dwrow + 4 * i + 3, hi.y);
    }

    out[OFF_IDX + gid] = (float)bidx;   // < 1024, exactly representable

    // block-reduce loss partial -> one global atomic per block
#pragma unroll
    for (int o = 16; o > 0; o >>= 1)
        lsum += __shfl_xor_sync(0xFFFFFFFFu, lsum, o);
    if ((tid & 31) == 0) s_red[tid >> 5] = lsum;
    __syncthreads();
    if (tid == 0) {
        float t = 0.f;
#pragma unroll
        for (int w = 0; w < TPB / 32; w++) t += s_red[w];
        atomicAdd(&g_loss, t);
    }

    // flush block-local counts
    for (int i = tid; i < K_CB; i += TPB) {
        float v = s_counts[i];
        if (v != 0.0f) atomicAdd(&g_counts[i], v);
    }
}

// ---------------------------------------------------------------------------
// Stage 1 of finalize: new_cluster_size, n-reduction, loss. One block.
// ---------------------------------------------------------------------------
__global__ void __launch_bounds__(K_CB)
vq_ncs_kernel(const float* __restrict__ ema_cs, float* __restrict__ out) {
    __shared__ float s_n[K_CB];
    const int k = threadIdx.x;

    float ncs = DECAY * ema_cs[k] + (1.0f - DECAY) * g_counts[k];
    out[OFF_CS + k] = ncs;

    s_n[k] = ncs;
    __syncthreads();
#pragma unroll
    for (int s = K_CB / 2; s > 0; s >>= 1) {
        if (k < s) s_n[k] += s_n[k + s];
        __syncthreads();
    }
    if (k == 0) {
        g_n = s_n[0];
        out[OFF_LOSS] = COMMIT * g_loss / (float)((size_t)N_TOK * D_EMB);
    }
}

// ---------------------------------------------------------------------------
// Stage 2 of finalize: element-parallel EMA weight + codebook update.
// ---------------------------------------------------------------------------
__global__ void __launch_bounds__(256)
vq_update_kernel(const float* __restrict__ ema_w, float* __restrict__ out) {
    const int idx = blockIdx.x * 256 + threadIdx.x;   // 0 .. K*D-1
    const int k = idx >> 6;

    float ncs = out[OFF_CS + k];
    float n = g_n;
    float smoothed = (ncs + EPSV) / (n + (float)K_CB * EPSV) * n;

    float w = DECAY * ema_w[idx] + (1.0f - DECAY) * g_dw[idx];
    out[OFF_EW + idx] = w;
    out[OFF_CB + idx] = w / smoothed;
}

// ---------------------------------------------------------------------------
extern "C" void kernel_launch(void* const* d_in, const int* in_sizes, int n_in,
                              void* d_out, int out_size) {
    const float* inputs   = (const float*)d_in[0];
    const float* codebook = (const float*)d_in[1];
    const float* ema_cs   = (const float*)d_in[2];
    const float* ema_w    = (const float*)d_in[3];
    float* out = (float*)d_out;

    vq_zero_kernel<<<(K_CB * D_EMB + 255) / 256, 256>>>();
    vq_cnorm_kernel<<<(K_CB + 255) / 256, 256>>>(codebook);
    vq_assign_kernel<<<N_TOK / TPB, TPB>>>(inputs, codebook, out);
    vq_ncs_kernel<<<1, K_CB>>>(ema_cs, out);
    vq_update_kernel<<<(K_CB * D_EMB) / 256, 256>>>(ema_w, out);
}

// round 5
// speedup vs baseline: 1.5700x; 1.4518x over previous
#include <cuda_runtime.h>

// Problem constants
#define N_TOK  262144
#define K_CB   1024
#define D_EMB  64
#define DECAY  0.99f
#define EPSV   1e-5f
#define COMMIT 0.25f

// Output layout (float32 blob, reference return order)
#define OFF_Q    0
#define OFF_LOSS 16777216
#define OFF_IDX  16777217
#define OFF_CB   17039361   // odd -> only 4-byte aligned
#define OFF_CS   17104897
#define OFF_EW   17105921   // odd -> only 4-byte aligned

// Scratch (device globals; no allocations allowed)
__device__ float g_dw[K_CB * D_EMB];
__device__ float g_counts[K_CB];
__device__ float g_loss;
__device__ float g_cnorm[K_CB];
__device__ float g_n;

typedef unsigned long long u64;

// ---- packed f32x2 helpers (per-lane IEEE rounding == scalar FFMA) ----------
__device__ __forceinline__ void ffma2(u64& d, u64 a, u64 b) {
    asm("fma.rn.f32x2 %0, %1, %2, %0;" : "+l"(d) : "l"(a), "l"(b));
}
__device__ __forceinline__ float2 unpack2(u64 v) {
    float2 r; asm("mov.b64 {%0, %1}, %2;" : "=f"(r.x), "=f"(r.y) : "l"(v)); return r;
}

// ---------------------------------------------------------------------------
// Zero scratch (graph replays require determinism)
// ---------------------------------------------------------------------------
__global__ void vq_zero_kernel() {
    int i = blockIdx.x * blockDim.x + threadIdx.x;
    if (i < K_CB * D_EMB) g_dw[i] = 0.0f;
    if (i < K_CB)         g_counts[i] = 0.0f;
    if (i == 0)           g_loss = 0.0f;
}

// ---------------------------------------------------------------------------
// Precompute ||c||^2 per code (identical arithmetic to R2)
// ---------------------------------------------------------------------------
__global__ void vq_cnorm_kernel(const float* __restrict__ codebook) {
    int k = blockIdx.x * blockDim.x + threadIdx.x;
    if (k >= K_CB) return;
    const float4* c = reinterpret_cast<const float4*>(codebook + k * D_EMB);
    float s0 = 0.f, s1 = 0.f, s2 = 0.f, s3 = 0.f;
#pragma unroll
    for (int i = 0; i < D_EMB / 4; i++) {
        float4 v = c[i];
        s0 += v.x * v.x; s1 += v.y * v.y;
        s2 += v.z * v.z; s3 += v.w * v.w;
    }
    g_cnorm[k] = (s0 + s1) + (s2 + s3);
}

// ---------------------------------------------------------------------------
// Main fused kernel, 2 tokens per thread. Each token's accumulation chains
// are bit-identical to the validated R2/R4 ordering:
//   lane-x of aXY == s0 chain, lane-y == s1; aZW -> (s2,s3);
//   dot = (s0+s1)+(s2+s3); d = cn - 2.0f*dot; strict-< first-min.
// The 16 broadcast LDS.128 per code now feed 64 FFMA2 (2 tokens) instead
// of 32 -> halves the shared-memory pipe load per token.
// ---------------------------------------------------------------------------
#define TPB   128
#define CHUNK 128

__global__ void __launch_bounds__(TPB, 3)
vq_assign_kernel(const float* __restrict__ inputs,
                 const float* __restrict__ codebook,
                 float* __restrict__ out) {
    __shared__ float s_c[CHUNK * D_EMB];   // 32 KB code chunk
    __shared__ float s_cn[CHUNK];
    __shared__ float s_counts[K_CB];       // 4 KB per-block count aggregation
    __shared__ float s_red[TPB / 32];

    const int tid = threadIdx.x;
    const int gidA = blockIdx.x * (2 * TPB) + tid;     // token A
    const int gidB = gidA + TPB;                       // token B (coalesced pair)

    for (int i = tid; i < K_CB; i += TPB) s_counts[i] = 0.0f;

    // load both input vectors as packed f32x2 pairs
    ulonglong2 xa[16], xb[16];
    const ulonglong2* xpA = reinterpret_cast<const ulonglong2*>(inputs + (size_t)gidA * D_EMB);
    const ulonglong2* xpB = reinterpret_cast<const ulonglong2*>(inputs + (size_t)gidB * D_EMB);
#pragma unroll
    for (int i = 0; i < 16; i++) { xa[i] = xpA[i]; xb[i] = xpB[i]; }

    float bestA = 3.4028235e38f, bestB = 3.4028235e38f;
    int   bidxA = 0,             bidxB = 0;

    for (int ch = 0; ch < K_CB / CHUNK; ch++) {
        __syncthreads();
        const float4* cp = reinterpret_cast<const float4*>(codebook + (size_t)ch * CHUNK * D_EMB);
        float4* scp = reinterpret_cast<float4*>(s_c);
#pragma unroll
        for (int i = 0; i < (CHUNK * D_EMB / 4) / TPB; i++)
            scp[tid + i * TPB] = cp[tid + i * TPB];
        if (tid < CHUNK) s_cn[tid] = g_cnorm[ch * CHUNK + tid];
        __syncthreads();

#pragma unroll 2
        for (int j = 0; j < CHUNK; j++) {
            const ulonglong2* csh = reinterpret_cast<const ulonglong2*>(s_c + j * D_EMB);
            u64 aXY0 = 0, aZW0 = 0, aXY1 = 0, aZW1 = 0;
#pragma unroll
            for (int i = 0; i < 16; i++) {
                ulonglong2 c2 = csh[i];   // LDS.128 broadcast, shared by both tokens
                ffma2(aXY0, xa[i].x, c2.x);
                ffma2(aZW0, xa[i].y, c2.y);
                ffma2(aXY1, xb[i].x, c2.x);
                ffma2(aZW1, xb[i].y, c2.y);
            }
            float cn = s_cn[j];
            {
                float2 uxy = unpack2(aXY0);
                float2 uzw = unpack2(aZW0);
                float dot = (uxy.x + uxy.y) + (uzw.x + uzw.y);
                float d = cn - 2.0f * dot;
                if (d < bestA) { bestA = d; bidxA = ch * CHUNK + j; }
            }
            {
                float2 uxy = unpack2(aXY1);
                float2 uzw = unpack2(aZW1);
                float dot = (uxy.x + uxy.y) + (uzw.x + uzw.y);
                float d = cn - 2.0f * dot;
                if (d < bestB) { bestB = d; bidxB = ch * CHUNK + j; }
            }
        }
    }

    // per-block count aggregation
    atomicAdd(&s_counts[bidxA], 1.0f);
    atomicAdd(&s_counts[bidxB], 1.0f);

    // gather + quantized store + loss + dw for both tokens
    float lsum = 0.0f;
    {
        const float4* cch = reinterpret_cast<const float4*>(codebook + (size_t)bidxA * D_EMB);
        float4* qout = reinterpret_cast<float4*>(out + OFF_Q + (size_t)gidA * D_EMB);
        float* dwrow = g_dw + (size_t)bidxA * D_EMB;
#pragma unroll
        for (int i = 0; i < 16; i++) {
            float4 c4 = cch[i];
            qout[i] = c4;
            float2 lo = unpack2(xa[i].x);
            float2 hi = unpack2(xa[i].y);
            float dx = c4.x - lo.x, dy = c4.y - lo.y;
            float dz = c4.z - hi.x, dwv = c4.w - hi.y;
            lsum += dx * dx + dy * dy + dz * dz + dwv * dwv;
            atomicAdd(dwrow + 4 * i + 0, lo.x);
            atomicAdd(dwrow + 4 * i + 1, lo.y);
            atomicAdd(dwrow + 4 * i + 2, hi.x);
            atomicAdd(dwrow + 4 * i + 3, hi.y);
        }
        out[OFF_IDX + gidA] = (float)bidxA;
    }
    {
        const float4* cch = reinterpret_cast<const float4*>(codebook + (size_t)bidxB * D_EMB);
        float4* qout = reinterpret_cast<float4*>(out + OFF_Q + (size_t)gidB * D_EMB);
        float* dwrow = g_dw + (size_t)bidxB * D_EMB;
#pragma unroll
        for (int i = 0; i < 16; i++) {
            float4 c4 = cch[i];
            qout[i] = c4;
            float2 lo = unpack2(xb[i].x);
            float2 hi = unpack2(xb[i].y);
            float dx = c4.x - lo.x, dy = c4.y - lo.y;
            float dz = c4.z - hi.x, dwv = c4.w - hi.y;
            lsum += dx * dx + dy * dy + dz * dz + dwv * dwv;
            atomicAdd(dwrow + 4 * i + 0, lo.x);
            atomicAdd(dwrow + 4 * i + 1, lo.y);
            atomicAdd(dwrow + 4 * i + 2, hi.x);
            atomicAdd(dwrow + 4 * i + 3, hi.y);
        }
        out[OFF_IDX + gidB] = (float)bidxB;
    }

    // block-reduce loss partial -> one global atomic per block
#pragma unroll
    for (int o = 16; o > 0; o >>= 1)
        lsum += __shfl_xor_sync(0xFFFFFFFFu, lsum, o);
    if ((tid & 31) == 0) s_red[tid >> 5] = lsum;
    __syncthreads();
    if (tid == 0) {
        float t = 0.f;
#pragma unroll
        for (int w = 0; w < TPB / 32; w++) t += s_red[w];
        atomicAdd(&g_loss, t);
    }

    // flush block-local counts
    for (int i = tid; i < K_CB; i += TPB) {
        float v = s_counts[i];
        if (v != 0.0f) atomicAdd(&g_counts[i], v);
    }
}

// ---------------------------------------------------------------------------
// Stage 1 of finalize: new_cluster_size, n-reduction, loss. One block.
// ---------------------------------------------------------------------------
__global__ void __launch_bounds__(K_CB)
vq_ncs_kernel(const float* __restrict__ ema_cs, float* __restrict__ out) {
    __shared__ float s_n[K_CB];
    const int k = threadIdx.x;

    float ncs = DECAY * ema_cs[k] + (1.0f - DECAY) * g_counts[k];
    out[OFF_CS + k] = ncs;

    s_n[k] = ncs;
    __syncthreads();
#pragma unroll
    for (int s = K_CB / 2; s > 0; s >>= 1) {
        if (k < s) s_n[k] += s_n[k + s];
        __syncthreads();
    }
    if (k == 0) {
        g_n = s_n[0];
        out[OFF_LOSS] = COMMIT * g_loss / (float)((size_t)N_TOK * D_EMB);
    }
}

// ---------------------------------------------------------------------------
// Stage 2 of finalize: element-parallel EMA weight + codebook update.
// ---------------------------------------------------------------------------
__global__ void __launch_bounds__(256)
vq_update_kernel(const float* __restrict__ ema_w, float* __restrict__ out) {
    const int idx = blockIdx.x * 256 + threadIdx.x;   // 0 .. K*D-1
    const int k = idx >> 6;

    float ncs = out[OFF_CS + k];
    float n = g_n;
    float smoothed = (ncs + EPSV) / (n + (float)K_CB * EPSV) * n;

    float w = DECAY * ema_w[idx] + (1.0f - DECAY) * g_dw[idx];
    out[OFF_EW + idx] = w;
    out[OFF_CB + idx] = w / smoothed;
}

// ---------------------------------------------------------------------------
extern "C" void kernel_launch(void* const* d_in, const int* in_sizes, int n_in,
                              void* d_out, int out_size) {
    const float* inputs   = (const float*)d_in[0];
    const float* codebook = (const float*)d_in[1];
    const float* ema_cs   = (const float*)d_in[2];
    const float* ema_w    = (const float*)d_in[3];
    float* out = (float*)d_out;

    vq_zero_kernel<<<(K_CB * D_EMB + 255) / 256, 256>>>();
    vq_cnorm_kernel<<<(K_CB + 255) / 256, 256>>>(codebook);
    vq_assign_kernel<<<N_TOK / (2 * TPB), TPB>>>(inputs, codebook, out);
    vq_ncs_kernel<<<1, K_CB>>>(ema_cs, out);
    vq_update_kernel<<<(K_CB * D_EMB) / 256, 256>>>(ema_w, out);
}